// round 14
// baseline (speedup 1.0000x reference)
#include <cuda_runtime.h>
#include <cuda_fp16.h>
#include <cstdint>

// Shapes
#define BB     8
#define NHEADS 12
#define HD     32
#define NW     64
#define WSQ    144
#define MROWS  73728        // BB*NW*WSQ
#define QKV_N  1152
#define LOG2E  1.4426950408889634f

// Scratch (allocation-free rule: __device__ globals)
__device__ __half g_qh[MROWS * 384];   // per-head [B,NW,H,144,32] fp16
__device__ __half g_kh[MROWS * 384];   // per-head [B,NW,H,144,32] fp16
__device__ __half g_vh[MROWS * 384];   // per-head [B,NW,H,144,32] fp16
__device__ __half g_xh[MROWS * 384];   // rolled/windowed x, fp16
__device__ __half g_atth[MROWS * 384]; // attention out, fp16
__device__ __half g_wqh[384 * QKV_N];  // weights fp16
__device__ __half g_woh[384 * 384];

// ---------------------------------------------------------------------------
// helpers
// ---------------------------------------------------------------------------
__device__ __forceinline__ uint32_t smem_u32(const void* p) {
    return (uint32_t)__cvta_generic_to_shared(p);
}
__device__ __forceinline__ void ldsmx4(uint32_t& r0, uint32_t& r1, uint32_t& r2,
                                       uint32_t& r3, uint32_t a) {
    asm volatile("ldmatrix.sync.aligned.m8n8.x4.shared.b16 {%0,%1,%2,%3}, [%4];"
                 : "=r"(r0), "=r"(r1), "=r"(r2), "=r"(r3) : "r"(a));
}
__device__ __forceinline__ void ldsmx4t(uint32_t& r0, uint32_t& r1, uint32_t& r2,
                                        uint32_t& r3, uint32_t a) {
    asm volatile("ldmatrix.sync.aligned.m8n8.x4.trans.shared.b16 {%0,%1,%2,%3}, [%4];"
                 : "=r"(r0), "=r"(r1), "=r"(r2), "=r"(r3) : "r"(a));
}
__device__ __forceinline__ void mma_f16(float* c, const uint32_t* a,
                                        uint32_t b0, uint32_t b1) {
    asm volatile(
        "mma.sync.aligned.m16n8k16.row.col.f32.f16.f16.f32 "
        "{%0,%1,%2,%3},{%4,%5,%6,%7},{%8,%9},{%0,%1,%2,%3};"
        : "+f"(c[0]), "+f"(c[1]), "+f"(c[2]), "+f"(c[3])
        : "r"(a[0]), "r"(a[1]), "r"(a[2]), "r"(a[3]), "r"(b0), "r"(b1));
}
// packs (lo, hi) floats into one fp16x2 register with a single CVT
__device__ __forceinline__ uint32_t cvt2h(float lo, float hi) {
    uint32_t r;
    asm("cvt.rn.f16x2.f32 %0, %1, %2;" : "=r"(r) : "f"(hi), "f"(lo));
    return r;
}
__device__ __forceinline__ void cpasync16(void* s, const void* g) {
    asm volatile("cp.async.cg.shared.global [%0], [%1], 16;"
                 :: "r"(smem_u32(s)), "l"(g));
}
__device__ __forceinline__ float ex2f(float x) {
    float r;
    asm("ex2.approx.f32 %0, %1;" : "=f"(r) : "f"(x));
    return r;
}

#define AST  40      // A smem row stride (fp16 elems): 80 B -> conflict-free
#define BST  72      // B smem row stride (64-wide tile): 144 B = 9*16 -> conflict-free
#define A_STAGE 5120 // 128*AST
#define B_STAGE 2304 // 32*BST
#define NST  4
#define SMEM_G   ((NST * A_STAGE + NST * B_STAGE) * 2)       // 59392

// ---------------------------------------------------------------------------
// Merged prep kernel: roll-gather x -> fp16, weights -> fp16
// ---------------------------------------------------------------------------
__global__ __launch_bounds__(256) void prep_all(const float* __restrict__ X,
                                                const float* __restrict__ wqkv,
                                                const float* __restrict__ wout) {
    const int bid = blockIdx.x;
    if (bid < 27648) {
        const int id = bid * 256 + threadIdx.x;   // float4 id
        const int r = id / 96, t = id - r * 96;
        int b = r / 9216; int rem = r - b * 9216;
        int w = rem / 144; int i = rem - w * 144;
        int y = (w >> 3) * 12 + i / 12 + 6; if (y >= 96) y -= 96;
        int x = (w & 7) * 12 + i % 12 + 6;  if (x >= 96) x -= 96;
        float4 v = *((const float4*)(X + ((b * 96 + y) * 96 + x) * 384) + t);
        int o = r * 384 + t * 4;
        *(uint32_t*)(g_xh + o)     = cvt2h(v.x, v.y);
        *(uint32_t*)(g_xh + o + 2) = cvt2h(v.z, v.w);
    } else {
        const int id = (bid - 27648) * 256 + threadIdx.x;
        float4 v;
        __half* oh; int o;
        if (id < 110592) {                        // 384*1152/4
            v = ((const float4*)wqkv)[id];
            oh = g_wqh; o = id * 4;
        } else {
            int id2 = id - 110592;                // < 36864
            v = ((const float4*)wout)[id2];
            oh = g_woh; o = id2 * 4;
        }
        *(uint32_t*)(oh + o)     = cvt2h(v.x, v.y);
        *(uint32_t*)(oh + o + 2) = cvt2h(v.z, v.w);
    }
}

// ---------------------------------------------------------------------------
// GEMM: 128x64 tile, BK=32, 256 thr, 8 warps (4m x 2n, 32x32 warp tile).
// Single fp16 mma. 4-stage cp.async pipeline. 3 CTAs/SM.
// ---------------------------------------------------------------------------
__device__ __forceinline__ void load_stage(
    const __half* __restrict__ Ag, const __half* __restrict__ Bg,
    __half* Ah, __half* Bh,
    int m0, int n0, int ldb, int k0, int st, int tid)
{
    __half* ash = Ah + st * A_STAGE;
    __half* bsh = Bh + st * B_STAGE;
#pragma unroll
    for (int q = 0; q < 2; q++) {
        int c = tid * 2 + q;
        int row = c >> 2, ch = (c & 3) * 8;                 // A: 128 x 32
        cpasync16(ash + row * AST + ch, Ag + (m0 + row) * 384 + k0 + ch);
    }
    {
        int c = tid;                                        // B: 32 x 64
        int row = c >> 3, ch = (c & 7) * 8;
        cpasync16(bsh + row * BST + ch, Bg + (k0 + row) * ldb + n0 + ch);
    }
}

__device__ __forceinline__ void compute_stage(
    const __half* Ah, const __half* Bh,
    int wm, int wn, int lane, float acc[2][4][4])
{
#pragma unroll
    for (int ks = 0; ks < 2; ks++) {
        const int kk = ks * 16;
        uint32_t ah[2][4], bh[2][4];
        const int arow = wm + (lane & 15);
        const int acol = kk + (lane >> 4) * 8;
#pragma unroll
        for (int mt = 0; mt < 2; mt++) {
            ldsmx4(ah[mt][0], ah[mt][1], ah[mt][2], ah[mt][3],
                   smem_u32(Ah + (arow + mt * 16) * AST + acol));
        }
        const int bk = kk + (lane & 15);
        const int bnb = wn + (lane >> 4) * 8;
#pragma unroll
        for (int g = 0; g < 2; g++) {
            ldsmx4t(bh[g][0], bh[g][1], bh[g][2], bh[g][3],
                    smem_u32(Bh + bk * BST + bnb + g * 16));
        }
#pragma unroll
        for (int mt = 0; mt < 2; mt++)
#pragma unroll
            for (int g = 0; g < 2; g++)
#pragma unroll
                for (int hf = 0; hf < 2; hf++) {
                    mma_f16(acc[mt][2 * g + hf], ah[mt],
                            bh[g][2 * hf], bh[g][2 * hf + 1]);
                }
    }
}

#define GEMM_MAINLOOP(AG, BG, LDB)                                               \
    extern __shared__ __align__(16) __half smem[];                               \
    __half* Ah = smem;                                                           \
    __half* Bh = smem + NST * A_STAGE;                                           \
    const int tid = threadIdx.x;                                                 \
    const int m0 = blockIdx.y * 128;                                             \
    const int n0 = blockIdx.x * 64;                                              \
    const int wid = tid >> 5, lane = tid & 31;                                   \
    const int wm = (wid >> 1) * 32;                                              \
    const int wn = (wid & 1) * 32;                                               \
    float acc[2][4][4];                                                          \
    _Pragma("unroll") for (int a_ = 0; a_ < 2; a_++)                             \
    _Pragma("unroll") for (int b_ = 0; b_ < 4; b_++)                             \
    _Pragma("unroll") for (int c_ = 0; c_ < 4; c_++) acc[a_][b_][c_] = 0.f;      \
    _Pragma("unroll") for (int s_ = 0; s_ < NST - 1; s_++) {                     \
        load_stage(AG, BG, Ah, Bh, m0, n0, LDB, s_ * 32, s_, tid);               \
        asm volatile("cp.async.commit_group;" ::: "memory");                     \
    }                                                                            \
    for (int it = 0; it < 12; it++) {                                            \
        asm volatile("cp.async.wait_group %0;" :: "n"(NST - 2) : "memory");      \
        __syncthreads();                                                         \
        if (it < 12 - (NST - 1)) {                                               \
            load_stage(AG, BG, Ah, Bh, m0, n0, LDB,                              \
                       (it + NST - 1) * 32, (it + NST - 1) & (NST - 1), tid);    \
        }                                                                        \
        asm volatile("cp.async.commit_group;" ::: "memory");                     \
        const int st = it & (NST - 1);                                           \
        compute_stage(Ah + st * A_STAGE, Bh + st * B_STAGE, wm, wn, lane, acc);  \
    }

// ---------------------------------------------------------------------------
// Kernel: QKV GEMM (1 fp16 mma) -> Q,K,V fp16 row-major per-head.
// ---------------------------------------------------------------------------
__global__ __launch_bounds__(256, 3) void qkv_gemm_mma() {
    GEMM_MAINLOOP(g_xh, g_wqh, QKV_N)

    const int part = n0 / 384;                // 0=Q, 1=K, 2=V
    const int cbase = n0 - part * 384;
    __half* outp = (part == 0) ? g_qh : (part == 1 ? g_kh : g_vh);

#pragma unroll
    for (int mt = 0; mt < 2; mt++) {
#pragma unroll
        for (int rr = 0; rr < 2; rr++) {
            int r = m0 + wm + mt * 16 + (lane >> 2) + rr * 8;
            int b = r / 9216; int rem = r - b * 9216;
            int w = rem / 144; int i = rem - w * 144;
            int bw12 = (b * 64 + w) * 12;
#pragma unroll
            for (int nt = 0; nt < 4; nt++) {
                int c = cbase + wn + nt * 8 + (lane & 3) * 2;
                int h = c >> 5, d = c & 31;
                int tq = ((bw12 + h) * 144 + i) * 32 + d;
                *(uint32_t*)(outp + tq) =
                    cvt2h(acc[mt][nt][rr * 2], acc[mt][nt][rr * 2 + 1]);
            }
        }
    }
}

// ---------------------------------------------------------------------------
// Kernel: flash-chunked attention; block = (b, w, head-group of 4).
// Tables built once per block; K/V double-buffered across heads via cp.async.
// ---------------------------------------------------------------------------
#define VST  40
#define KV_BUF (WSQ * VST)                 // 5760 halfs per tile

__global__ __launch_bounds__(288, 2) void attn_mma(const int* __restrict__ pixmap,
                                                   const float* __restrict__ posemb,
                                                   const float* __restrict__ pixemb) {
    extern __shared__ __align__(16) char smemraw[];
    __half* Ksh   = (__half*)smemraw;                 // [2][KV_BUF]
    __half* Vsh   = Ksh + 2 * KV_BUF;                 // [2][KV_BUF]
    float*  pose  = (float*)(Vsh + 2 * KV_BUF);       // 529
    float*  MASKP = pose + 529;                       // 8*144
    float*  pmv   = MASKP + 8 * WSQ;                  // 144
    int*    jinfo = (int*)(pmv + WSQ);                // 144

    const int tid = threadIdx.x;
    const int b = blockIdx.y;
    const int w = blockIdx.x / 3;
    const int hg = blockIdx.x - w * 3;                // head group: heads 4hg..4hg+3
    const int hbase = ((b * 64 + w) * 12 + hg * 4) * 4608;
    const bool ul = (w >> 3) == 7;
    const bool lr = (w & 7) == 7;

    // issue head 0 K/V
#pragma unroll
    for (int q = 0; q < 2; q++) {
        int cix = tid + q * 288;                 // < 576
        int j = cix >> 2, ch = (cix & 3) * 8;
        cpasync16(Ksh + j * VST + ch, g_kh + hbase + j * 32 + ch);
        cpasync16(Vsh + j * VST + ch, g_vh + hbase + j * 32 + ch);
    }
    asm volatile("cp.async.commit_group;" ::: "memory");

    // per-block tables (head-independent)
    for (int f = tid; f < 529; f += 288) pose[f] = posemb[f] * LOG2E;
    if (tid < 144) {
        int wy = w >> 3, wx = w & 7;
        int iy = tid / 12, ix = tid - iy * 12;
        float pm = (float)pixmap[(b * 96 + wy * 12 + iy) * 96 + wx * 12 + ix];
        pmv[tid] = pm;
        jinfo[tid] = iy * 23 + ix;
        float pe0 = pixemb[0] * LOG2E, pe1 = pixemb[1] * LOG2E;
        bool jh = tid >= 72, jxh = ix >= 6;
#pragma unroll
        for (int cls = 0; cls < 4; cls++) {
            bool m = (ul && (jh != (bool)(cls >> 1))) || (lr && (jxh != (bool)(cls & 1)));
            float base = m ? -1e30f : 0.f;
            MASKP[(cls * 2 + 0) * 144 + tid] = base + pe0;
            MASKP[(cls * 2 + 1) * 144 + tid] = base + ((pm != 0.f) ? pe1 : pe0);
        }
    }

    const int wr = tid >> 5;
    const int lane = tid & 31;
    const int g = lane >> 2, t = lane & 3;
    const int i0 = wr * 16 + g, i1 = i0 + 8;
    const int iy0 = i0 / 12, ix0 = i0 - iy0 * 12;
    const int iy1 = i1 / 12, ix1 = i1 - iy1 * 12;
    const float* pr0 = pose + (11 - iy0) * 23 + (11 - ix0);
    const float* pr1 = pose + (11 - iy1) * 23 + (11 - ix1);
    const float scale2 = 0.17677669529663689f * LOG2E;

    bool rowsel_done = false;
    const float* mr0 = nullptr;
    const float* mr1 = nullptr;

    for (int hh = 0; hh < 4; hh++) {
        // prefetch next head's K/V into the other buffer
        if (hh < 3) {
            const int nb = hbase + (hh + 1) * 4608;
            __half* kd = Ksh + ((hh + 1) & 1) * KV_BUF;
            __half* vd = Vsh + ((hh + 1) & 1) * KV_BUF;
#pragma unroll
            for (int q = 0; q < 2; q++) {
                int cix = tid + q * 288;
                int j = cix >> 2, ch = (cix & 3) * 8;
                cpasync16(kd + j * VST + ch, g_kh + nb + j * 32 + ch);
                cpasync16(vd + j * VST + ch, g_vh + nb + j * 32 + ch);
            }
        }
        asm volatile("cp.async.commit_group;" ::: "memory");
        asm volatile("cp.async.wait_group 1;" ::: "memory");
        __syncthreads();

        if (!rowsel_done) {   // needs pmv (written above, visible after sync)
            const int a0 = (pmv[i0] != 0.f) ? 1 : 0;
            const int a1 = (pmv[i1] != 0.f) ? 1 : 0;
            mr0 = MASKP + (((i0 >= 72 ? 2 : 0) + (ix0 >= 6 ? 1 : 0)) * 2 + a0) * 144;
            mr1 = MASKP + (((i1 >= 72 ? 2 : 0) + (ix1 >= 6 ? 1 : 0)) * 2 + a1) * 144;
            rowsel_done = true;
        }

        const int tb2 = hbase + hh * 4608;
        const __half* Kc = Ksh + (hh & 1) * KV_BUF;
        const __half* Vc = Vsh + (hh & 1) * KV_BUF;

        // Q fragments for this head
        uint32_t qh[2][4];
#pragma unroll
        for (int kc = 0; kc < 2; kc++) {
            int o0 = tb2 + i0 * 32 + kc * 16 + 2 * t;
            int o1 = tb2 + i1 * 32 + kc * 16 + 2 * t;
            qh[kc][0] = *(const uint32_t*)(g_qh + o0);
            qh[kc][1] = *(const uint32_t*)(g_qh + o1);
            qh[kc][2] = *(const uint32_t*)(g_qh + o0 + 8);
            qh[kc][3] = *(const uint32_t*)(g_qh + o1 + 8);
        }

        float oacc[4][4];
#pragma unroll
        for (int nt = 0; nt < 4; nt++)
#pragma unroll
            for (int c = 0; c < 4; c++) oacc[nt][c] = 0.f;
        float rs0 = 0.f, rs1 = 0.f;

#pragma unroll
        for (int jc = 0; jc < 9; jc++) {
            // S chunk via non-trans ldmatrix on row-major K [n=j][k=d]
            float sc[2][4];
#pragma unroll
            for (int u = 0; u < 2; u++)
#pragma unroll
                for (int c = 0; c < 4; c++) sc[u][c] = 0.f;

            const int jr = jc * 16 + ((lane >> 4) & 1) * 8 + (lane & 7);
            const int dbl = ((lane >> 3) & 1) * 8;
#pragma unroll
            for (int kc = 0; kc < 2; kc++) {
                uint32_t bh[4];
                ldsmx4(bh[0], bh[1], bh[2], bh[3],
                       smem_u32(Kc + jr * VST + kc * 16 + dbl));
                mma_f16(sc[0], qh[kc], bh[0], bh[1]);
                mma_f16(sc[1], qh[kc], bh[2], bh[3]);
            }

            // softmax chunk
#pragma unroll
            for (int u = 0; u < 2; u++) {
#pragma unroll
                for (int fc = 0; fc < 2; fc++) {
                    int j = jc * 16 + u * 8 + 2 * t + fc;
                    int poff = jinfo[j];
                    {
                        float p = ex2f(sc[u][fc] * scale2 + mr0[j] + pr0[poff]);
                        sc[u][fc] = p; rs0 += p;
                    }
                    {
                        float p = ex2f(sc[u][fc + 2] * scale2 + mr1[j] + pr1[poff]);
                        sc[u][fc + 2] = p; rs1 += p;
                    }
                }
            }

            // P -> fp16 A fragments (single-CVT packs), accumulate P@V
            uint32_t ph[4];
            ph[0] = cvt2h(sc[0][0], sc[0][1]);
            ph[1] = cvt2h(sc[0][2], sc[0][3]);
            ph[2] = cvt2h(sc[1][0], sc[1][1]);
            ph[3] = cvt2h(sc[1][2], sc[1][3]);
#pragma unroll
            for (int ng = 0; ng < 2; ng++) {
                uint32_t bv[4];
                uint32_t av_ = smem_u32(Vc + (jc * 16 + (lane & 15)) * VST +
                                        ng * 16 + (lane >> 4) * 8);
                ldsmx4t(bv[0], bv[1], bv[2], bv[3], av_);
                mma_f16(oacc[2 * ng],     ph, bv[0], bv[1]);
                mma_f16(oacc[2 * ng + 1], ph, bv[2], bv[3]);
            }
        }

        rs0 += __shfl_xor_sync(0xffffffff, rs0, 1);
        rs0 += __shfl_xor_sync(0xffffffff, rs0, 2);
        rs1 += __shfl_xor_sync(0xffffffff, rs1, 1);
        rs1 += __shfl_xor_sync(0xffffffff, rs1, 2);
        const float inv0 = 1.f / rs0, inv1 = 1.f / rs1;

        // write normalized output as fp16 for the out-proj GEMM
        const int hcol = (hg * 4 + hh) * 32;
        const int orow0 = ((b * 64 + w) * 144 + i0) * 384 + hcol;
        const int orow1 = ((b * 64 + w) * 144 + i1) * 384 + hcol;
#pragma unroll
        for (int nt = 0; nt < 4; nt++) {
            int col = nt * 8 + 2 * t;
            *(uint32_t*)(g_atth + orow0 + col) =
                cvt2h(oacc[nt][0] * inv0, oacc[nt][1] * inv0);
            *(uint32_t*)(g_atth + orow1 + col) =
                cvt2h(oacc[nt][2] * inv1, oacc[nt][3] * inv1);
        }
        __syncthreads();   // protect K/V buffer reuse by next prefetch
    }
}
#define SMEM_ATT (4 * KV_BUF * 2 + (529 + 8 * WSQ + WSQ) * 4 + WSQ * 4 + 16)

// ---------------------------------------------------------------------------
// Kernel: output projection (single fp16 mma) + bias + roll(+6,+6) scatter
// ---------------------------------------------------------------------------
__global__ __launch_bounds__(256, 3) void out_gemm_mma(const float* __restrict__ bout,
                                                       float* __restrict__ Out) {
    GEMM_MAINLOOP(g_atth, g_woh, 384)

#pragma unroll
    for (int mt = 0; mt < 2; mt++) {
#pragma unroll
        for (int rr = 0; rr < 2; rr++) {
            int r = m0 + wm + mt * 16 + (lane >> 2) + rr * 8;
            int b = r / 9216; int rem = r - b * 9216;
            int w = rem / 144; int i = rem - w * 144;
            int iy = i / 12, ix = i - iy * 12;
            int y = (w >> 3) * 12 + iy + 6; if (y >= 96) y -= 96;
            int x = (w & 7) * 12 + ix + 6;  if (x >= 96) x -= 96;
            float* orow = Out + ((b * 96 + y) * 96 + x) * 384;
#pragma unroll
            for (int nt = 0; nt < 4; nt++) {
                int c = n0 + wn + nt * 8 + (lane & 3) * 2;
                float2 bi = *(const float2*)(bout + c);
                float2 v = make_float2(acc[mt][nt][rr * 2] + bi.x,
                                       acc[mt][nt][rr * 2 + 1] + bi.y);
                *(float2*)(orow + c) = v;
            }
        }
    }
}

// ---------------------------------------------------------------------------
extern "C" void kernel_launch(void* const* d_in, const int* in_sizes, int n_in,
                              void* d_out, int out_size) {
    (void)in_sizes; (void)n_in; (void)out_size;
    const float* x      = (const float*)d_in[0];
    const int*   pixmap = (const int*)d_in[1];
    const float* wqkv   = (const float*)d_in[2];
    const float* posemb = (const float*)d_in[3];
    const float* pixemb = (const float*)d_in[4];
    const float* wout   = (const float*)d_in[5];
    const float* bout   = (const float*)d_in[6];
    float* out = (float*)d_out;

    cudaFuncSetAttribute(qkv_gemm_mma, cudaFuncAttributeMaxDynamicSharedMemorySize,
                         SMEM_G);
    cudaFuncSetAttribute(attn_mma, cudaFuncAttributeMaxDynamicSharedMemorySize,
                         SMEM_ATT);
    cudaFuncSetAttribute(out_gemm_mma, cudaFuncAttributeMaxDynamicSharedMemorySize,
                         SMEM_G);

    prep_all<<<28224, 256>>>(x, wqkv, wout);
    qkv_gemm_mma<<<dim3(18, MROWS / 128), 256, SMEM_G>>>();
    attn_mma<<<dim3(NW * 3, BB), 288, SMEM_ATT>>>(pixmap, posemb, pixemb);
    out_gemm_mma<<<dim3(6, MROWS / 128), 256, SMEM_G>>>(bout, out);
}

// round 15
// speedup vs baseline: 1.4172x; 1.4172x over previous
#include <cuda_runtime.h>
#include <cuda_fp16.h>
#include <cstdint>

// Shapes
#define BB     8
#define NHEADS 12
#define HD     32
#define NW     64
#define WSQ    144
#define MROWS  73728        // BB*NW*WSQ
#define QKV_N  1152
#define LOG2E  1.4426950408889634f

// Scratch (allocation-free rule: __device__ globals)
__device__ __half g_qh[MROWS * 384];   // per-head [B,NW,H,144,32] fp16
__device__ __half g_kh[MROWS * 384];   // per-head [B,NW,H,144,32] fp16
__device__ __half g_vh[MROWS * 384];   // per-head [B,NW,H,144,32] fp16
__device__ __half g_xh[MROWS * 384];   // rolled/windowed x, fp16
__device__ __half g_atth[MROWS * 384]; // attention out, fp16
__device__ __half g_wqh[384 * QKV_N];  // weights fp16
__device__ __half g_woh[384 * 384];

// ---------------------------------------------------------------------------
// helpers
// ---------------------------------------------------------------------------
__device__ __forceinline__ uint32_t smem_u32(const void* p) {
    return (uint32_t)__cvta_generic_to_shared(p);
}
__device__ __forceinline__ void ldsmx4(uint32_t& r0, uint32_t& r1, uint32_t& r2,
                                       uint32_t& r3, uint32_t a) {
    asm volatile("ldmatrix.sync.aligned.m8n8.x4.shared.b16 {%0,%1,%2,%3}, [%4];"
                 : "=r"(r0), "=r"(r1), "=r"(r2), "=r"(r3) : "r"(a));
}
__device__ __forceinline__ void ldsmx4t(uint32_t& r0, uint32_t& r1, uint32_t& r2,
                                        uint32_t& r3, uint32_t a) {
    asm volatile("ldmatrix.sync.aligned.m8n8.x4.trans.shared.b16 {%0,%1,%2,%3}, [%4];"
                 : "=r"(r0), "=r"(r1), "=r"(r2), "=r"(r3) : "r"(a));
}
__device__ __forceinline__ void mma_f16(float* c, const uint32_t* a,
                                        uint32_t b0, uint32_t b1) {
    asm volatile(
        "mma.sync.aligned.m16n8k16.row.col.f32.f16.f16.f32 "
        "{%0,%1,%2,%3},{%4,%5,%6,%7},{%8,%9},{%0,%1,%2,%3};"
        : "+f"(c[0]), "+f"(c[1]), "+f"(c[2]), "+f"(c[3])
        : "r"(a[0]), "r"(a[1]), "r"(a[2]), "r"(a[3]), "r"(b0), "r"(b1));
}
// packs (lo, hi) floats into one fp16x2 register with a single CVT
__device__ __forceinline__ uint32_t cvt2h(float lo, float hi) {
    uint32_t r;
    asm("cvt.rn.f16x2.f32 %0, %1, %2;" : "=r"(r) : "f"(hi), "f"(lo));
    return r;
}
__device__ __forceinline__ void cpasync16(void* s, const void* g) {
    asm volatile("cp.async.cg.shared.global [%0], [%1], 16;"
                 :: "r"(smem_u32(s)), "l"(g));
}
__device__ __forceinline__ float ex2f(float x) {
    float r;
    asm("ex2.approx.f32 %0, %1;" : "=f"(r) : "f"(x));
    return r;
}

// GEMM tiling: 128x128 tile, BK=64, 2 stages
#define AST  72      // A smem row stride (BK=64): 144 B = 9*16 -> conflict-free
#define BST  136     // B smem row stride: 272 B = 17*16 -> conflict-free
#define A_STAGE 9216 // 128*AST
#define B_STAGE 8704 // 64*BST
#define NST  2
#define SMEM_G   ((NST * A_STAGE + NST * B_STAGE) * 2)       // 71680

// ---------------------------------------------------------------------------
// Merged prep kernel: roll-gather x -> fp16, weights -> fp16
// ---------------------------------------------------------------------------
__global__ __launch_bounds__(256) void prep_all(const float* __restrict__ X,
                                                const float* __restrict__ wqkv,
                                                const float* __restrict__ wout) {
    const int bid = blockIdx.x;
    if (bid < 27648) {
        const int id = bid * 256 + threadIdx.x;   // float4 id
        const int r = id / 96, t = id - r * 96;
        int b = r / 9216; int rem = r - b * 9216;
        int w = rem / 144; int i = rem - w * 144;
        int y = (w >> 3) * 12 + i / 12 + 6; if (y >= 96) y -= 96;
        int x = (w & 7) * 12 + i % 12 + 6;  if (x >= 96) x -= 96;
        float4 v = *((const float4*)(X + ((b * 96 + y) * 96 + x) * 384) + t);
        int o = r * 384 + t * 4;
        *(uint32_t*)(g_xh + o)     = cvt2h(v.x, v.y);
        *(uint32_t*)(g_xh + o + 2) = cvt2h(v.z, v.w);
    } else {
        const int id = (bid - 27648) * 256 + threadIdx.x;
        float4 v;
        __half* oh; int o;
        if (id < 110592) {                        // 384*1152/4
            v = ((const float4*)wqkv)[id];
            oh = g_wqh; o = id * 4;
        } else {
            int id2 = id - 110592;                // < 36864
            v = ((const float4*)wout)[id2];
            oh = g_woh; o = id2 * 4;
        }
        *(uint32_t*)(oh + o)     = cvt2h(v.x, v.y);
        *(uint32_t*)(oh + o + 2) = cvt2h(v.z, v.w);
    }
}

// ---------------------------------------------------------------------------
// GEMM: 128x128 tile, BK=64, 256 thr, 8 warps (4m x 2n, 32x64 warp tile).
// Single fp16 mma. 2-stage cp.async pipeline, 6 K-iterations.
// ---------------------------------------------------------------------------
__device__ __forceinline__ void load_stage(
    const __half* __restrict__ Ag, const __half* __restrict__ Bg,
    __half* Ah, __half* Bh,
    int m0, int n0, int ldb, int k0, int st, int tid)
{
    __half* ash = Ah + st * A_STAGE;
    __half* bsh = Bh + st * B_STAGE;
#pragma unroll
    for (int q = 0; q < 4; q++) {
        int c = tid * 4 + q;
        int row = c >> 3, ch = (c & 7) * 8;                 // A: 128 x 64
        cpasync16(ash + row * AST + ch, Ag + (m0 + row) * 384 + k0 + ch);
    }
#pragma unroll
    for (int q = 0; q < 4; q++) {
        int c = tid * 4 + q;
        int row = c >> 4, ch = (c & 15) * 8;                // B: 64 x 128
        cpasync16(bsh + row * BST + ch, Bg + (k0 + row) * ldb + n0 + ch);
    }
}

__device__ __forceinline__ void compute_stage(
    const __half* Ah, const __half* Bh,
    int wm, int wn, int lane, float acc[2][8][4])
{
#pragma unroll
    for (int ks = 0; ks < 4; ks++) {
        const int kk = ks * 16;
        uint32_t ah[2][4], bh[4][4];
        const int arow = wm + (lane & 15);
        const int acol = kk + (lane >> 4) * 8;
#pragma unroll
        for (int mt = 0; mt < 2; mt++) {
            ldsmx4(ah[mt][0], ah[mt][1], ah[mt][2], ah[mt][3],
                   smem_u32(Ah + (arow + mt * 16) * AST + acol));
        }
        const int bk = kk + (lane & 15);
        const int bnb = wn + (lane >> 4) * 8;
#pragma unroll
        for (int g = 0; g < 4; g++) {
            ldsmx4t(bh[g][0], bh[g][1], bh[g][2], bh[g][3],
                    smem_u32(Bh + bk * BST + bnb + g * 16));
        }
#pragma unroll
        for (int mt = 0; mt < 2; mt++)
#pragma unroll
            for (int g = 0; g < 4; g++)
#pragma unroll
                for (int hf = 0; hf < 2; hf++) {
                    mma_f16(acc[mt][2 * g + hf], ah[mt],
                            bh[g][2 * hf], bh[g][2 * hf + 1]);
                }
    }
}

#define GEMM_MAINLOOP(AG, BG, LDB)                                               \
    extern __shared__ __align__(16) __half smem[];                               \
    __half* Ah = smem;                                                           \
    __half* Bh = smem + NST * A_STAGE;                                           \
    const int tid = threadIdx.x;                                                 \
    const int m0 = blockIdx.y * 128;                                             \
    const int n0 = blockIdx.x * 128;                                             \
    const int wid = tid >> 5, lane = tid & 31;                                   \
    const int wm = (wid >> 1) * 32;                                              \
    const int wn = (wid & 1) * 64;                                               \
    float acc[2][8][4];                                                          \
    _Pragma("unroll") for (int a_ = 0; a_ < 2; a_++)                             \
    _Pragma("unroll") for (int b_ = 0; b_ < 8; b_++)                             \
    _Pragma("unroll") for (int c_ = 0; c_ < 4; c_++) acc[a_][b_][c_] = 0.f;      \
    load_stage(AG, BG, Ah, Bh, m0, n0, LDB, 0, 0, tid);                          \
    asm volatile("cp.async.commit_group;" ::: "memory");                         \
    for (int it = 0; it < 6; it++) {                                             \
        asm volatile("cp.async.wait_group 0;" ::: "memory");                     \
        __syncthreads();                                                         \
        if (it < 5) {                                                            \
            load_stage(AG, BG, Ah, Bh, m0, n0, LDB,                              \
                       (it + 1) * 64, (it + 1) & 1, tid);                        \
        }                                                                        \
        asm volatile("cp.async.commit_group;" ::: "memory");                     \
        const int st = it & 1;                                                   \
        compute_stage(Ah + st * A_STAGE, Bh + st * B_STAGE, wm, wn, lane, acc);  \
    }

// ---------------------------------------------------------------------------
// Kernel: QKV GEMM (1 fp16 mma) -> Q,K,V fp16 row-major per-head.
// ---------------------------------------------------------------------------
__global__ __launch_bounds__(256, 2) void qkv_gemm_mma() {
    GEMM_MAINLOOP(g_xh, g_wqh, QKV_N)

    const int part = n0 / 384;                // 0=Q, 1=K, 2=V
    const int cbase = n0 - part * 384;
    __half* outp = (part == 0) ? g_qh : (part == 1 ? g_kh : g_vh);

#pragma unroll
    for (int mt = 0; mt < 2; mt++) {
#pragma unroll
        for (int rr = 0; rr < 2; rr++) {
            int r = m0 + wm + mt * 16 + (lane >> 2) + rr * 8;
            int b = r / 9216; int rem = r - b * 9216;
            int w = rem / 144; int i = rem - w * 144;
            int bw12 = (b * 64 + w) * 12;
#pragma unroll
            for (int nt = 0; nt < 8; nt++) {
                int c = cbase + wn + nt * 8 + (lane & 3) * 2;
                int h = c >> 5, d = c & 31;
                int tq = ((bw12 + h) * 144 + i) * 32 + d;
                *(uint32_t*)(outp + tq) =
                    cvt2h(acc[mt][nt][rr * 2], acc[mt][nt][rr * 2 + 1]);
            }
        }
    }
}

// ---------------------------------------------------------------------------
// Kernel: flash-chunked attention; block = (b, w, head-group of 4).
// Tables built once per block; K/V double-buffered across heads via cp.async.
// ---------------------------------------------------------------------------
#define VST  40
#define KV_BUF (WSQ * VST)                 // 5760 halfs per tile

__global__ __launch_bounds__(288, 2) void attn_mma(const int* __restrict__ pixmap,
                                                   const float* __restrict__ posemb,
                                                   const float* __restrict__ pixemb) {
    extern __shared__ __align__(16) char smemraw[];
    __half* Ksh   = (__half*)smemraw;                 // [2][KV_BUF]
    __half* Vsh   = Ksh + 2 * KV_BUF;                 // [2][KV_BUF]
    float*  pose  = (float*)(Vsh + 2 * KV_BUF);       // 529
    float*  MASKP = pose + 529;                       // 8*144
    float*  pmv   = MASKP + 8 * WSQ;                  // 144
    int*    jinfo = (int*)(pmv + WSQ);                // 144

    const int tid = threadIdx.x;
    const int b = blockIdx.y;
    const int w = blockIdx.x / 3;
    const int hg = blockIdx.x - w * 3;                // head group: heads 4hg..4hg+3
    const int hbase = ((b * 64 + w) * 12 + hg * 4) * 4608;
    const bool ul = (w >> 3) == 7;
    const bool lr = (w & 7) == 7;

    // issue head 0 K/V
#pragma unroll
    for (int q = 0; q < 2; q++) {
        int cix = tid + q * 288;                 // < 576
        int j = cix >> 2, ch = (cix & 3) * 8;
        cpasync16(Ksh + j * VST + ch, g_kh + hbase + j * 32 + ch);
        cpasync16(Vsh + j * VST + ch, g_vh + hbase + j * 32 + ch);
    }
    asm volatile("cp.async.commit_group;" ::: "memory");

    // per-block tables (head-independent)
    for (int f = tid; f < 529; f += 288) pose[f] = posemb[f] * LOG2E;
    if (tid < 144) {
        int wy = w >> 3, wx = w & 7;
        int iy = tid / 12, ix = tid - iy * 12;
        float pm = (float)pixmap[(b * 96 + wy * 12 + iy) * 96 + wx * 12 + ix];
        pmv[tid] = pm;
        jinfo[tid] = iy * 23 + ix;
        float pe0 = pixemb[0] * LOG2E, pe1 = pixemb[1] * LOG2E;
        bool jh = tid >= 72, jxh = ix >= 6;
#pragma unroll
        for (int cls = 0; cls < 4; cls++) {
            bool m = (ul && (jh != (bool)(cls >> 1))) || (lr && (jxh != (bool)(cls & 1)));
            float base = m ? -1e30f : 0.f;
            MASKP[(cls * 2 + 0) * 144 + tid] = base + pe0;
            MASKP[(cls * 2 + 1) * 144 + tid] = base + ((pm != 0.f) ? pe1 : pe0);
        }
    }

    const int wr = tid >> 5;
    const int lane = tid & 31;
    const int g = lane >> 2, t = lane & 3;
    const int i0 = wr * 16 + g, i1 = i0 + 8;
    const int iy0 = i0 / 12, ix0 = i0 - iy0 * 12;
    const int iy1 = i1 / 12, ix1 = i1 - iy1 * 12;
    const float* pr0 = pose + (11 - iy0) * 23 + (11 - ix0);
    const float* pr1 = pose + (11 - iy1) * 23 + (11 - ix1);
    const float scale2 = 0.17677669529663689f * LOG2E;

    bool rowsel_done = false;
    const float* mr0 = nullptr;
    const float* mr1 = nullptr;

    for (int hh = 0; hh < 4; hh++) {
        // prefetch next head's K/V into the other buffer
        if (hh < 3) {
            const int nb = hbase + (hh + 1) * 4608;
            __half* kd = Ksh + ((hh + 1) & 1) * KV_BUF;
            __half* vd = Vsh + ((hh + 1) & 1) * KV_BUF;
#pragma unroll
            for (int q = 0; q < 2; q++) {
                int cix = tid + q * 288;
                int j = cix >> 2, ch = (cix & 3) * 8;
                cpasync16(kd + j * VST + ch, g_kh + nb + j * 32 + ch);
                cpasync16(vd + j * VST + ch, g_vh + nb + j * 32 + ch);
            }
        }
        asm volatile("cp.async.commit_group;" ::: "memory");
        asm volatile("cp.async.wait_group 1;" ::: "memory");
        __syncthreads();

        if (!rowsel_done) {   // needs pmv (written above, visible after sync)
            const int a0 = (pmv[i0] != 0.f) ? 1 : 0;
            const int a1 = (pmv[i1] != 0.f) ? 1 : 0;
            mr0 = MASKP + (((i0 >= 72 ? 2 : 0) + (ix0 >= 6 ? 1 : 0)) * 2 + a0) * 144;
            mr1 = MASKP + (((i1 >= 72 ? 2 : 0) + (ix1 >= 6 ? 1 : 0)) * 2 + a1) * 144;
            rowsel_done = true;
        }

        const int tb2 = hbase + hh * 4608;
        const __half* Kc = Ksh + (hh & 1) * KV_BUF;
        const __half* Vc = Vsh + (hh & 1) * KV_BUF;

        // Q fragments for this head
        uint32_t qh[2][4];
#pragma unroll
        for (int kc = 0; kc < 2; kc++) {
            int o0 = tb2 + i0 * 32 + kc * 16 + 2 * t;
            int o1 = tb2 + i1 * 32 + kc * 16 + 2 * t;
            qh[kc][0] = *(const uint32_t*)(g_qh + o0);
            qh[kc][1] = *(const uint32_t*)(g_qh + o1);
            qh[kc][2] = *(const uint32_t*)(g_qh + o0 + 8);
            qh[kc][3] = *(const uint32_t*)(g_qh + o1 + 8);
        }

        float oacc[4][4];
#pragma unroll
        for (int nt = 0; nt < 4; nt++)
#pragma unroll
            for (int c = 0; c < 4; c++) oacc[nt][c] = 0.f;
        float rs0 = 0.f, rs1 = 0.f;

#pragma unroll
        for (int jc = 0; jc < 9; jc++) {
            // S chunk via non-trans ldmatrix on row-major K [n=j][k=d]
            float sc[2][4];
#pragma unroll
            for (int u = 0; u < 2; u++)
#pragma unroll
                for (int c = 0; c < 4; c++) sc[u][c] = 0.f;

            const int jr = jc * 16 + ((lane >> 4) & 1) * 8 + (lane & 7);
            const int dbl = ((lane >> 3) & 1) * 8;
#pragma unroll
            for (int kc = 0; kc < 2; kc++) {
                uint32_t bh[4];
                ldsmx4(bh[0], bh[1], bh[2], bh[3],
                       smem_u32(Kc + jr * VST + kc * 16 + dbl));
                mma_f16(sc[0], qh[kc], bh[0], bh[1]);
                mma_f16(sc[1], qh[kc], bh[2], bh[3]);
            }

            // softmax chunk
#pragma unroll
            for (int u = 0; u < 2; u++) {
#pragma unroll
                for (int fc = 0; fc < 2; fc++) {
                    int j = jc * 16 + u * 8 + 2 * t + fc;
                    int poff = jinfo[j];
                    {
                        float p = ex2f(sc[u][fc] * scale2 + mr0[j] + pr0[poff]);
                        sc[u][fc] = p; rs0 += p;
                    }
                    {
                        float p = ex2f(sc[u][fc + 2] * scale2 + mr1[j] + pr1[poff]);
                        sc[u][fc + 2] = p; rs1 += p;
                    }
                }
            }

            // P -> fp16 A fragments (single-CVT packs), accumulate P@V
            uint32_t ph[4];
            ph[0] = cvt2h(sc[0][0], sc[0][1]);
            ph[1] = cvt2h(sc[0][2], sc[0][3]);
            ph[2] = cvt2h(sc[1][0], sc[1][1]);
            ph[3] = cvt2h(sc[1][2], sc[1][3]);
#pragma unroll
            for (int ng = 0; ng < 2; ng++) {
                uint32_t bv[4];
                uint32_t av_ = smem_u32(Vc + (jc * 16 + (lane & 15)) * VST +
                                        ng * 16 + (lane >> 4) * 8);
                ldsmx4t(bv[0], bv[1], bv[2], bv[3], av_);
                mma_f16(oacc[2 * ng],     ph, bv[0], bv[1]);
                mma_f16(oacc[2 * ng + 1], ph, bv[2], bv[3]);
            }
        }

        rs0 += __shfl_xor_sync(0xffffffff, rs0, 1);
        rs0 += __shfl_xor_sync(0xffffffff, rs0, 2);
        rs1 += __shfl_xor_sync(0xffffffff, rs1, 1);
        rs1 += __shfl_xor_sync(0xffffffff, rs1, 2);
        const float inv0 = 1.f / rs0, inv1 = 1.f / rs1;

        // write normalized output as fp16 for the out-proj GEMM
        const int hcol = (hg * 4 + hh) * 32;
        const int orow0 = ((b * 64 + w) * 144 + i0) * 384 + hcol;
        const int orow1 = ((b * 64 + w) * 144 + i1) * 384 + hcol;
#pragma unroll
        for (int nt = 0; nt < 4; nt++) {
            int col = nt * 8 + 2 * t;
            *(uint32_t*)(g_atth + orow0 + col) =
                cvt2h(oacc[nt][0] * inv0, oacc[nt][1] * inv0);
            *(uint32_t*)(g_atth + orow1 + col) =
                cvt2h(oacc[nt][2] * inv1, oacc[nt][3] * inv1);
        }
        __syncthreads();   // protect K/V buffer reuse by next prefetch
    }
}
#define SMEM_ATT (4 * KV_BUF * 2 + (529 + 8 * WSQ + WSQ) * 4 + WSQ * 4 + 16)

// ---------------------------------------------------------------------------
// Kernel: output projection (single fp16 mma) + bias + roll(+6,+6) scatter
// ---------------------------------------------------------------------------
__global__ __launch_bounds__(256, 2) void out_gemm_mma(const float* __restrict__ bout,
                                                       float* __restrict__ Out) {
    GEMM_MAINLOOP(g_atth, g_woh, 384)

#pragma unroll
    for (int mt = 0; mt < 2; mt++) {
#pragma unroll
        for (int rr = 0; rr < 2; rr++) {
            int r = m0 + wm + mt * 16 + (lane >> 2) + rr * 8;
            int b = r / 9216; int rem = r - b * 9216;
            int w = rem / 144; int i = rem - w * 144;
            int iy = i / 12, ix = i - iy * 12;
            int y = (w >> 3) * 12 + iy + 6; if (y >= 96) y -= 96;
            int x = (w & 7) * 12 + ix + 6;  if (x >= 96) x -= 96;
            float* orow = Out + ((b * 96 + y) * 96 + x) * 384;
#pragma unroll
            for (int nt = 0; nt < 8; nt++) {
                int c = n0 + wn + nt * 8 + (lane & 3) * 2;
                float2 bi = *(const float2*)(bout + c);
                float2 v = make_float2(acc[mt][nt][rr * 2] + bi.x,
                                       acc[mt][nt][rr * 2 + 1] + bi.y);
                *(float2*)(orow + c) = v;
            }
        }
    }
}

// ---------------------------------------------------------------------------
extern "C" void kernel_launch(void* const* d_in, const int* in_sizes, int n_in,
                              void* d_out, int out_size) {
    (void)in_sizes; (void)n_in; (void)out_size;
    const float* x      = (const float*)d_in[0];
    const int*   pixmap = (const int*)d_in[1];
    const float* wqkv   = (const float*)d_in[2];
    const float* posemb = (const float*)d_in[3];
    const float* pixemb = (const float*)d_in[4];
    const float* wout   = (const float*)d_in[5];
    const float* bout   = (const float*)d_in[6];
    float* out = (float*)d_out;

    cudaFuncSetAttribute(qkv_gemm_mma, cudaFuncAttributeMaxDynamicSharedMemorySize,
                         SMEM_G);
    cudaFuncSetAttribute(attn_mma, cudaFuncAttributeMaxDynamicSharedMemorySize,
                         SMEM_ATT);
    cudaFuncSetAttribute(out_gemm_mma, cudaFuncAttributeMaxDynamicSharedMemorySize,
                         SMEM_G);

    prep_all<<<28224, 256>>>(x, wqkv, wout);
    qkv_gemm_mma<<<dim3(9, MROWS / 128), 256, SMEM_G>>>();
    attn_mma<<<dim3(NW * 3, BB), 288, SMEM_ATT>>>(pixmap, posemb, pixemb);
    out_gemm_mma<<<dim3(3, MROWS / 128), 256, SMEM_G>>>(bout, out);
}

// round 16
// speedup vs baseline: 1.6640x; 1.1742x over previous
#include <cuda_runtime.h>
#include <cuda_fp16.h>
#include <cstdint>

// Shapes
#define BB     8
#define NHEADS 12
#define HD     32
#define NW     64
#define WSQ    144
#define MROWS  73728        // BB*NW*WSQ
#define QKV_N  1152
#define LOG2E  1.4426950408889634f

// Scratch (allocation-free rule: __device__ globals)
__device__ __half g_qh[MROWS * 384];   // per-head [B,NW,H,144,32] fp16
__device__ __half g_kh[MROWS * 384];   // per-head [B,NW,H,144,32] fp16
__device__ __half g_vh[MROWS * 384];   // per-head [B,NW,H,144,32] fp16
__device__ __half g_xh[MROWS * 384];   // rolled/windowed x, fp16
__device__ __half g_atth[MROWS * 384]; // attention out, fp16
__device__ __half g_wqh[384 * QKV_N];  // weights fp16
__device__ __half g_woh[384 * 384];

// ---------------------------------------------------------------------------
// helpers
// ---------------------------------------------------------------------------
__device__ __forceinline__ uint32_t smem_u32(const void* p) {
    return (uint32_t)__cvta_generic_to_shared(p);
}
__device__ __forceinline__ void ldsmx4(uint32_t& r0, uint32_t& r1, uint32_t& r2,
                                       uint32_t& r3, uint32_t a) {
    asm volatile("ldmatrix.sync.aligned.m8n8.x4.shared.b16 {%0,%1,%2,%3}, [%4];"
                 : "=r"(r0), "=r"(r1), "=r"(r2), "=r"(r3) : "r"(a));
}
__device__ __forceinline__ void ldsmx4t(uint32_t& r0, uint32_t& r1, uint32_t& r2,
                                        uint32_t& r3, uint32_t a) {
    asm volatile("ldmatrix.sync.aligned.m8n8.x4.trans.shared.b16 {%0,%1,%2,%3}, [%4];"
                 : "=r"(r0), "=r"(r1), "=r"(r2), "=r"(r3) : "r"(a));
}
__device__ __forceinline__ void mma_f16(float* c, const uint32_t* a,
                                        uint32_t b0, uint32_t b1) {
    asm volatile(
        "mma.sync.aligned.m16n8k16.row.col.f32.f16.f16.f32 "
        "{%0,%1,%2,%3},{%4,%5,%6,%7},{%8,%9},{%0,%1,%2,%3};"
        : "+f"(c[0]), "+f"(c[1]), "+f"(c[2]), "+f"(c[3])
        : "r"(a[0]), "r"(a[1]), "r"(a[2]), "r"(a[3]), "r"(b0), "r"(b1));
}
// packs (lo, hi) floats into one fp16x2 register with a single CVT
__device__ __forceinline__ uint32_t cvt2h(float lo, float hi) {
    uint32_t r;
    asm("cvt.rn.f16x2.f32 %0, %1, %2;" : "=r"(r) : "f"(hi), "f"(lo));
    return r;
}
__device__ __forceinline__ void cpasync16(void* s, const void* g) {
    asm volatile("cp.async.cg.shared.global [%0], [%1], 16;"
                 :: "r"(smem_u32(s)), "l"(g));
}
__device__ __forceinline__ float ex2f(float x) {
    float r;
    asm("ex2.approx.f32 %0, %1;" : "=f"(r) : "f"(x));
    return r;
}

// GEMM tiling: 128x128 tile, BK=32, 5 stages
#define AST  40      // A smem row stride (fp16 elems): 80 B -> conflict-free
#define BST  136     // B smem row stride: 272 B -> conflict-free
#define A_STAGE 5120 // 128*AST
#define B_STAGE 4352 // 32*BST
#define NST  5
#define SMEM_G   ((NST * A_STAGE + NST * B_STAGE) * 2)       // 94720

// ---------------------------------------------------------------------------
// Merged prep kernel: roll-gather x -> fp16, weights -> fp16
// ---------------------------------------------------------------------------
__global__ __launch_bounds__(256) void prep_all(const float* __restrict__ X,
                                                const float* __restrict__ wqkv,
                                                const float* __restrict__ wout) {
    const int bid = blockIdx.x;
    if (bid < 27648) {
        const int id = bid * 256 + threadIdx.x;   // float4 id
        const int r = id / 96, t = id - r * 96;
        int b = r / 9216; int rem = r - b * 9216;
        int w = rem / 144; int i = rem - w * 144;
        int y = (w >> 3) * 12 + i / 12 + 6; if (y >= 96) y -= 96;
        int x = (w & 7) * 12 + i % 12 + 6;  if (x >= 96) x -= 96;
        float4 v = *((const float4*)(X + ((b * 96 + y) * 96 + x) * 384) + t);
        int o = r * 384 + t * 4;
        *(uint32_t*)(g_xh + o)     = cvt2h(v.x, v.y);
        *(uint32_t*)(g_xh + o + 2) = cvt2h(v.z, v.w);
    } else {
        const int id = (bid - 27648) * 256 + threadIdx.x;
        float4 v;
        __half* oh; int o;
        if (id < 110592) {                        // 384*1152/4
            v = ((const float4*)wqkv)[id];
            oh = g_wqh; o = id * 4;
        } else {
            int id2 = id - 110592;                // < 36864
            v = ((const float4*)wout)[id2];
            oh = g_woh; o = id2 * 4;
        }
        *(uint32_t*)(oh + o)     = cvt2h(v.x, v.y);
        *(uint32_t*)(oh + o + 2) = cvt2h(v.z, v.w);
    }
}

// ---------------------------------------------------------------------------
// GEMM: 128x128 tile, BK=32, 256 thr, 8 warps (4m x 2n, 32x64 warp tile).
// Single fp16 mma. 5-stage cp.async pipeline, 12 K-iterations.
// ---------------------------------------------------------------------------
__device__ __forceinline__ void load_stage(
    const __half* __restrict__ Ag, const __half* __restrict__ Bg,
    __half* Ah, __half* Bh,
    int m0, int n0, int ldb, int k0, int st, int tid)
{
    __half* ash = Ah + st * A_STAGE;
    __half* bsh = Bh + st * B_STAGE;
#pragma unroll
    for (int q = 0; q < 2; q++) {
        int c = tid * 2 + q;
        int row = c >> 2, ch = (c & 3) * 8;                 // A: 128 x 32
        cpasync16(ash + row * AST + ch, Ag + (m0 + row) * 384 + k0 + ch);
    }
#pragma unroll
    for (int q = 0; q < 2; q++) {
        int c = tid * 2 + q;
        int row = c >> 4, ch = (c & 15) * 8;                // B: 32 x 128
        cpasync16(bsh + row * BST + ch, Bg + (k0 + row) * ldb + n0 + ch);
    }
}

__device__ __forceinline__ void compute_stage(
    const __half* Ah, const __half* Bh,
    int wm, int wn, int lane, float acc[2][8][4])
{
#pragma unroll
    for (int ks = 0; ks < 2; ks++) {
        const int kk = ks * 16;
        uint32_t ah[2][4], bh[4][4];
        const int arow = wm + (lane & 15);
        const int acol = kk + (lane >> 4) * 8;
#pragma unroll
        for (int mt = 0; mt < 2; mt++) {
            ldsmx4(ah[mt][0], ah[mt][1], ah[mt][2], ah[mt][3],
                   smem_u32(Ah + (arow + mt * 16) * AST + acol));
        }
        const int bk = kk + (lane & 15);
        const int bnb = wn + (lane >> 4) * 8;
#pragma unroll
        for (int g = 0; g < 4; g++) {
            ldsmx4t(bh[g][0], bh[g][1], bh[g][2], bh[g][3],
                    smem_u32(Bh + bk * BST + bnb + g * 16));
        }
#pragma unroll
        for (int mt = 0; mt < 2; mt++)
#pragma unroll
            for (int g = 0; g < 4; g++)
#pragma unroll
                for (int hf = 0; hf < 2; hf++) {
                    mma_f16(acc[mt][2 * g + hf], ah[mt],
                            bh[g][2 * hf], bh[g][2 * hf + 1]);
                }
    }
}

#define GEMM_MAINLOOP(AG, BG, LDB)                                               \
    extern __shared__ __align__(16) __half smem[];                               \
    __half* Ah = smem;                                                           \
    __half* Bh = smem + NST * A_STAGE;                                           \
    const int tid = threadIdx.x;                                                 \
    const int m0 = blockIdx.y * 128;                                             \
    const int n0 = blockIdx.x * 128;                                             \
    const int wid = tid >> 5, lane = tid & 31;                                   \
    const int wm = (wid >> 1) * 32;                                              \
    const int wn = (wid & 1) * 64;                                               \
    float acc[2][8][4];                                                          \
    _Pragma("unroll") for (int a_ = 0; a_ < 2; a_++)                             \
    _Pragma("unroll") for (int b_ = 0; b_ < 8; b_++)                             \
    _Pragma("unroll") for (int c_ = 0; c_ < 4; c_++) acc[a_][b_][c_] = 0.f;      \
    _Pragma("unroll") for (int s_ = 0; s_ < NST - 1; s_++) {                     \
        load_stage(AG, BG, Ah, Bh, m0, n0, LDB, s_ * 32, s_, tid);               \
        asm volatile("cp.async.commit_group;" ::: "memory");                     \
    }                                                                            \
    for (int it = 0; it < 12; it++) {                                            \
        asm volatile("cp.async.wait_group %0;" :: "n"(NST - 2) : "memory");      \
        __syncthreads();                                                         \
        if (it < 12 - (NST - 1)) {                                               \
            load_stage(AG, BG, Ah, Bh, m0, n0, LDB,                              \
                       (it + NST - 1) * 32, (it + NST - 1) % NST, tid);          \
        }                                                                        \
        asm volatile("cp.async.commit_group;" ::: "memory");                     \
        const int st = it % NST;                                                 \
        compute_stage(Ah + st * A_STAGE, Bh + st * B_STAGE, wm, wn, lane, acc);  \
    }

// ---------------------------------------------------------------------------
// Kernel: QKV GEMM (1 fp16 mma) -> Q,K,V fp16 row-major per-head.
// ---------------------------------------------------------------------------
__global__ __launch_bounds__(256, 2) void qkv_gemm_mma() {
    GEMM_MAINLOOP(g_xh, g_wqh, QKV_N)

    const int part = n0 / 384;                // 0=Q, 1=K, 2=V
    const int cbase = n0 - part * 384;
    __half* outp = (part == 0) ? g_qh : (part == 1 ? g_kh : g_vh);

#pragma unroll
    for (int mt = 0; mt < 2; mt++) {
#pragma unroll
        for (int rr = 0; rr < 2; rr++) {
            int r = m0 + wm + mt * 16 + (lane >> 2) + rr * 8;
            int b = r / 9216; int rem = r - b * 9216;
            int w = rem / 144; int i = rem - w * 144;
            int bw12 = (b * 64 + w) * 12;
#pragma unroll
            for (int nt = 0; nt < 8; nt++) {
                int c = cbase + wn + nt * 8 + (lane & 3) * 2;
                int h = c >> 5, d = c & 31;
                int tq = ((bw12 + h) * 144 + i) * 32 + d;
                *(uint32_t*)(outp + tq) =
                    cvt2h(acc[mt][nt][rr * 2], acc[mt][nt][rr * 2 + 1]);
            }
        }
    }
}

// ---------------------------------------------------------------------------
// Kernel: flash-chunked attention; block = (b, w, head-group of 4).
// Tables built once per block; K/V double-buffered across heads via cp.async.
// ---------------------------------------------------------------------------
#define VST  40
#define KV_BUF (WSQ * VST)                 // 5760 halfs per tile

__global__ __launch_bounds__(288, 2) void attn_mma(const int* __restrict__ pixmap,
                                                   const float* __restrict__ posemb,
                                                   const float* __restrict__ pixemb) {
    extern __shared__ __align__(16) char smemraw[];
    __half* Ksh   = (__half*)smemraw;                 // [2][KV_BUF]
    __half* Vsh   = Ksh + 2 * KV_BUF;                 // [2][KV_BUF]
    float*  pose  = (float*)(Vsh + 2 * KV_BUF);       // 529
    float*  MASKP = pose + 529;                       // 8*144
    float*  pmv   = MASKP + 8 * WSQ;                  // 144
    int*    jinfo = (int*)(pmv + WSQ);                // 144

    const int tid = threadIdx.x;
    const int b = blockIdx.y;
    const int w = blockIdx.x / 3;
    const int hg = blockIdx.x - w * 3;                // head group: heads 4hg..4hg+3
    const int hbase = ((b * 64 + w) * 12 + hg * 4) * 4608;
    const bool ul = (w >> 3) == 7;
    const bool lr = (w & 7) == 7;

    // issue head 0 K/V
#pragma unroll
    for (int q = 0; q < 2; q++) {
        int cix = tid + q * 288;                 // < 576
        int j = cix >> 2, ch = (cix & 3) * 8;
        cpasync16(Ksh + j * VST + ch, g_kh + hbase + j * 32 + ch);
        cpasync16(Vsh + j * VST + ch, g_vh + hbase + j * 32 + ch);
    }
    asm volatile("cp.async.commit_group;" ::: "memory");

    // per-block tables (head-independent)
    for (int f = tid; f < 529; f += 288) pose[f] = posemb[f] * LOG2E;
    if (tid < 144) {
        int wy = w >> 3, wx = w & 7;
        int iy = tid / 12, ix = tid - iy * 12;
        float pm = (float)pixmap[(b * 96 + wy * 12 + iy) * 96 + wx * 12 + ix];
        pmv[tid] = pm;
        jinfo[tid] = iy * 23 + ix;
        float pe0 = pixemb[0] * LOG2E, pe1 = pixemb[1] * LOG2E;
        bool jh = tid >= 72, jxh = ix >= 6;
#pragma unroll
        for (int cls = 0; cls < 4; cls++) {
            bool m = (ul && (jh != (bool)(cls >> 1))) || (lr && (jxh != (bool)(cls & 1)));
            float base = m ? -1e30f : 0.f;
            MASKP[(cls * 2 + 0) * 144 + tid] = base + pe0;
            MASKP[(cls * 2 + 1) * 144 + tid] = base + ((pm != 0.f) ? pe1 : pe0);
        }
    }

    const int wr = tid >> 5;
    const int lane = tid & 31;
    const int g = lane >> 2, t = lane & 3;
    const int i0 = wr * 16 + g, i1 = i0 + 8;
    const int iy0 = i0 / 12, ix0 = i0 - iy0 * 12;
    const int iy1 = i1 / 12, ix1 = i1 - iy1 * 12;
    const float* pr0 = pose + (11 - iy0) * 23 + (11 - ix0);
    const float* pr1 = pose + (11 - iy1) * 23 + (11 - ix1);
    const float scale2 = 0.17677669529663689f * LOG2E;

    bool rowsel_done = false;
    const float* mr0 = nullptr;
    const float* mr1 = nullptr;

    for (int hh = 0; hh < 4; hh++) {
        // prefetch next head's K/V into the other buffer
        if (hh < 3) {
            const int nb = hbase + (hh + 1) * 4608;
            __half* kd = Ksh + ((hh + 1) & 1) * KV_BUF;
            __half* vd = Vsh + ((hh + 1) & 1) * KV_BUF;
#pragma unroll
            for (int q = 0; q < 2; q++) {
                int cix = tid + q * 288;
                int j = cix >> 2, ch = (cix & 3) * 8;
                cpasync16(kd + j * VST + ch, g_kh + nb + j * 32 + ch);
                cpasync16(vd + j * VST + ch, g_vh + nb + j * 32 + ch);
            }
        }
        asm volatile("cp.async.commit_group;" ::: "memory");
        asm volatile("cp.async.wait_group 1;" ::: "memory");
        __syncthreads();

        if (!rowsel_done) {   // needs pmv (written above, visible after sync)
            const int a0 = (pmv[i0] != 0.f) ? 1 : 0;
            const int a1 = (pmv[i1] != 0.f) ? 1 : 0;
            mr0 = MASKP + (((i0 >= 72 ? 2 : 0) + (ix0 >= 6 ? 1 : 0)) * 2 + a0) * 144;
            mr1 = MASKP + (((i1 >= 72 ? 2 : 0) + (ix1 >= 6 ? 1 : 0)) * 2 + a1) * 144;
            rowsel_done = true;
        }

        const int tb2 = hbase + hh * 4608;
        const __half* Kc = Ksh + (hh & 1) * KV_BUF;
        const __half* Vc = Vsh + (hh & 1) * KV_BUF;

        // Q fragments for this head
        uint32_t qh[2][4];
#pragma unroll
        for (int kc = 0; kc < 2; kc++) {
            int o0 = tb2 + i0 * 32 + kc * 16 + 2 * t;
            int o1 = tb2 + i1 * 32 + kc * 16 + 2 * t;
            qh[kc][0] = *(const uint32_t*)(g_qh + o0);
            qh[kc][1] = *(const uint32_t*)(g_qh + o1);
            qh[kc][2] = *(const uint32_t*)(g_qh + o0 + 8);
            qh[kc][3] = *(const uint32_t*)(g_qh + o1 + 8);
        }

        float oacc[4][4];
#pragma unroll
        for (int nt = 0; nt < 4; nt++)
#pragma unroll
            for (int c = 0; c < 4; c++) oacc[nt][c] = 0.f;
        float rs0 = 0.f, rs1 = 0.f;

#pragma unroll
        for (int jc = 0; jc < 9; jc++) {
            // S chunk via non-trans ldmatrix on row-major K [n=j][k=d]
            float sc[2][4];
#pragma unroll
            for (int u = 0; u < 2; u++)
#pragma unroll
                for (int c = 0; c < 4; c++) sc[u][c] = 0.f;

            const int jr = jc * 16 + ((lane >> 4) & 1) * 8 + (lane & 7);
            const int dbl = ((lane >> 3) & 1) * 8;
#pragma unroll
            for (int kc = 0; kc < 2; kc++) {
                uint32_t bh[4];
                ldsmx4(bh[0], bh[1], bh[2], bh[3],
                       smem_u32(Kc + jr * VST + kc * 16 + dbl));
                mma_f16(sc[0], qh[kc], bh[0], bh[1]);
                mma_f16(sc[1], qh[kc], bh[2], bh[3]);
            }

            // softmax chunk
#pragma unroll
            for (int u = 0; u < 2; u++) {
#pragma unroll
                for (int fc = 0; fc < 2; fc++) {
                    int j = jc * 16 + u * 8 + 2 * t + fc;
                    int poff = jinfo[j];
                    {
                        float p = ex2f(sc[u][fc] * scale2 + mr0[j] + pr0[poff]);
                        sc[u][fc] = p; rs0 += p;
                    }
                    {
                        float p = ex2f(sc[u][fc + 2] * scale2 + mr1[j] + pr1[poff]);
                        sc[u][fc + 2] = p; rs1 += p;
                    }
                }
            }

            // P -> fp16 A fragments (single-CVT packs), accumulate P@V
            uint32_t ph[4];
            ph[0] = cvt2h(sc[0][0], sc[0][1]);
            ph[1] = cvt2h(sc[0][2], sc[0][3]);
            ph[2] = cvt2h(sc[1][0], sc[1][1]);
            ph[3] = cvt2h(sc[1][2], sc[1][3]);
#pragma unroll
            for (int ng = 0; ng < 2; ng++) {
                uint32_t bv[4];
                uint32_t av_ = smem_u32(Vc + (jc * 16 + (lane & 15)) * VST +
                                        ng * 16 + (lane >> 4) * 8);
                ldsmx4t(bv[0], bv[1], bv[2], bv[3], av_);
                mma_f16(oacc[2 * ng],     ph, bv[0], bv[1]);
                mma_f16(oacc[2 * ng + 1], ph, bv[2], bv[3]);
            }
        }

        rs0 += __shfl_xor_sync(0xffffffff, rs0, 1);
        rs0 += __shfl_xor_sync(0xffffffff, rs0, 2);
        rs1 += __shfl_xor_sync(0xffffffff, rs1, 1);
        rs1 += __shfl_xor_sync(0xffffffff, rs1, 2);
        const float inv0 = 1.f / rs0, inv1 = 1.f / rs1;

        // write normalized output as fp16 for the out-proj GEMM
        const int hcol = (hg * 4 + hh) * 32;
        const int orow0 = ((b * 64 + w) * 144 + i0) * 384 + hcol;
        const int orow1 = ((b * 64 + w) * 144 + i1) * 384 + hcol;
#pragma unroll
        for (int nt = 0; nt < 4; nt++) {
            int col = nt * 8 + 2 * t;
            *(uint32_t*)(g_atth + orow0 + col) =
                cvt2h(oacc[nt][0] * inv0, oacc[nt][1] * inv0);
            *(uint32_t*)(g_atth + orow1 + col) =
                cvt2h(oacc[nt][2] * inv1, oacc[nt][3] * inv1);
        }
        __syncthreads();   // protect K/V buffer reuse by next prefetch
    }
}
#define SMEM_ATT (4 * KV_BUF * 2 + (529 + 8 * WSQ + WSQ) * 4 + WSQ * 4 + 16)

// ---------------------------------------------------------------------------
// Kernel: output projection (single fp16 mma) + bias + roll(+6,+6) scatter
// ---------------------------------------------------------------------------
__global__ __launch_bounds__(256, 2) void out_gemm_mma(const float* __restrict__ bout,
                                                       float* __restrict__ Out) {
    GEMM_MAINLOOP(g_atth, g_woh, 384)

#pragma unroll
    for (int mt = 0; mt < 2; mt++) {
#pragma unroll
        for (int rr = 0; rr < 2; rr++) {
            int r = m0 + wm + mt * 16 + (lane >> 2) + rr * 8;
            int b = r / 9216; int rem = r - b * 9216;
            int w = rem / 144; int i = rem - w * 144;
            int iy = i / 12, ix = i - iy * 12;
            int y = (w >> 3) * 12 + iy + 6; if (y >= 96) y -= 96;
            int x = (w & 7) * 12 + ix + 6;  if (x >= 96) x -= 96;
            float* orow = Out + ((b * 96 + y) * 96 + x) * 384;
#pragma unroll
            for (int nt = 0; nt < 8; nt++) {
                int c = n0 + wn + nt * 8 + (lane & 3) * 2;
                float2 bi = *(const float2*)(bout + c);
                float2 v = make_float2(acc[mt][nt][rr * 2] + bi.x,
                                       acc[mt][nt][rr * 2 + 1] + bi.y);
                *(float2*)(orow + c) = v;
            }
        }
    }
}

// ---------------------------------------------------------------------------
extern "C" void kernel_launch(void* const* d_in, const int* in_sizes, int n_in,
                              void* d_out, int out_size) {
    (void)in_sizes; (void)n_in; (void)out_size;
    const float* x      = (const float*)d_in[0];
    const int*   pixmap = (const int*)d_in[1];
    const float* wqkv   = (const float*)d_in[2];
    const float* posemb = (const float*)d_in[3];
    const float* pixemb = (const float*)d_in[4];
    const float* wout   = (const float*)d_in[5];
    const float* bout   = (const float*)d_in[6];
    float* out = (float*)d_out;

    cudaFuncSetAttribute(qkv_gemm_mma, cudaFuncAttributeMaxDynamicSharedMemorySize,
                         SMEM_G);
    cudaFuncSetAttribute(attn_mma, cudaFuncAttributeMaxDynamicSharedMemorySize,
                         SMEM_ATT);
    cudaFuncSetAttribute(out_gemm_mma, cudaFuncAttributeMaxDynamicSharedMemorySize,
                         SMEM_G);

    prep_all<<<28224, 256>>>(x, wqkv, wout);
    qkv_gemm_mma<<<dim3(9, MROWS / 128), 256, SMEM_G>>>();
    attn_mma<<<dim3(NW * 3, BB), 288, SMEM_ATT>>>(pixmap, posemb, pixemb);
    out_gemm_mma<<<dim3(3, MROWS / 128), 256, SMEM_G>>>(bout, out);
}